// round 1
// baseline (speedup 1.0000x reference)
#include <cuda_runtime.h>

#define BSZ 32
#define CNT 128
#define Wd  2048
#define Pd  1024
#define Ed  8
#define Kc  25
#define Ld  2
#define ROWS (BSZ*CNT)   // 4096

// ---------------- scratch (device globals: allocation-free) ----------------
__device__ float g_c[ROWS*Wd];   // conv output (GEMM A input)
__device__ float g_x[ROWS*Wd];   // inter-layer x
__device__ float g_q[ROWS*Pd];
__device__ float g_k[ROWS*Pd];
__device__ float g_v[ROWS*Pd];
__device__ float g_p[ROWS*Pd];   // wv_real
__device__ float g_wavg[Ld*Kc];
__device__ float g_bavg[Ld];

// ---------------- average conv weights over experts ----------------
__global__ void avg_conv_kernel(const float* __restrict__ cw, const float* __restrict__ cb,
                                float* __restrict__ wavg, float* __restrict__ bavg) {
    int idx = threadIdx.x;
    if (idx < Ld * Kc) {
        int l = idx / Kc, kk = idx % Kc;
        float s = 0.f;
        #pragma unroll
        for (int e = 0; e < Ed; e++) s += cw[(l * Ed + e) * Kc + kk];
        wavg[idx] = s * (1.0f / Ed);
    }
    if (idx < Ld) {
        float s = 0.f;
        #pragma unroll
        for (int e = 0; e < Ed; e++) s += cb[idx * Ed + e];
        bavg[idx] = s * (1.0f / Ed);
    }
}

// ---------------- 1D conv, one row per block ----------------
__global__ __launch_bounds__(256) void conv_row_kernel(
    const float* __restrict__ X, float* __restrict__ Y,
    const float* __restrict__ wavg, const float* __restrict__ bavg)
{
    __shared__ float sx[Wd + Kc - 1];   // halo = 12 each side
    __shared__ float wsh[Kc];
    const int row = blockIdx.x;
    const int tid = threadIdx.x;
    const float* xr = X + (size_t)row * Wd;

    for (int i = tid; i < Wd + Kc - 1; i += 256) {
        int src = i - (Kc / 2);
        sx[i] = (src >= 0 && src < Wd) ? xr[src] : 0.0f;
    }
    if (tid < Kc) wsh[tid] = wavg[tid];
    __syncthreads();

    const float b = bavg[0];
    float* yr = Y + (size_t)row * Wd;
    for (int h = tid; h < Wd; h += 256) {
        float s = b;
        #pragma unroll
        for (int k = 0; k < Kc; k++) s += sx[h + k] * wsh[k];
        yr[h] = s;
    }
}

// ---------------- GEMM: C[M,N] = A[M,Kd] * B[N,Kd]^T + bias[N] ----------------
#define BM 128
#define BN 128
#define BKK 8

__global__ __launch_bounds__(256) void gemm_abt_kernel(
    const float* __restrict__ A, const float* __restrict__ B,
    const float* __restrict__ bias, float* __restrict__ C,
    int M, int N, int Kd)
{
    __shared__ float As[BKK][BM + 4];
    __shared__ float Bs[BKK][BN + 4];

    const int tid = threadIdx.x;
    const int bm = blockIdx.y * BM;
    const int bn = blockIdx.x * BN;
    const int lrow = tid >> 1;          // 0..127
    const int lk   = (tid & 1) * 4;     // 0 or 4
    const int tx = tid & 15;            // 0..15
    const int ty = tid >> 4;            // 0..15

    const float* Aptr = A + (size_t)(bm + lrow) * Kd + lk;
    const float* Bptr = B + (size_t)(bn + lrow) * Kd + lk;

    float acc[8][8];
    #pragma unroll
    for (int i = 0; i < 8; i++)
        #pragma unroll
        for (int j = 0; j < 8; j++) acc[i][j] = 0.0f;

    for (int k0 = 0; k0 < Kd; k0 += BKK) {
        float4 a4 = *(const float4*)(Aptr + k0);
        float4 b4 = *(const float4*)(Bptr + k0);
        As[lk + 0][lrow] = a4.x; As[lk + 1][lrow] = a4.y;
        As[lk + 2][lrow] = a4.z; As[lk + 3][lrow] = a4.w;
        Bs[lk + 0][lrow] = b4.x; Bs[lk + 1][lrow] = b4.y;
        Bs[lk + 2][lrow] = b4.z; Bs[lk + 3][lrow] = b4.w;
        __syncthreads();

        #pragma unroll
        for (int kk = 0; kk < BKK; kk++) {
            float ar[8], br[8];
            #pragma unroll
            for (int i = 0; i < 8; i++) ar[i] = As[kk][ty * 8 + i];
            #pragma unroll
            for (int j = 0; j < 8; j++) br[j] = Bs[kk][tx * 8 + j];
            #pragma unroll
            for (int i = 0; i < 8; i++)
                #pragma unroll
                for (int j = 0; j < 8; j++)
                    acc[i][j] += ar[i] * br[j];
        }
        __syncthreads();
    }

    float bb[8];
    #pragma unroll
    for (int j = 0; j < 8; j++) bb[j] = bias[bn + tx * 8 + j];

    #pragma unroll
    for (int i = 0; i < 8; i++) {
        float* Crow = C + (size_t)(bm + ty * 8 + i) * N + bn + tx * 8;
        float4 o0 = make_float4(acc[i][0] + bb[0], acc[i][1] + bb[1],
                                acc[i][2] + bb[2], acc[i][3] + bb[3]);
        float4 o1 = make_float4(acc[i][4] + bb[4], acc[i][5] + bb[5],
                                acc[i][6] + bb[6], acc[i][7] + bb[7]);
        *(float4*)(Crow)     = o0;
        *(float4*)(Crow + 4) = o1;
    }
}

// ---------------- FFT attention ----------------
__device__ __forceinline__ void fft1024_stages(float2* s, int tid, float sign) {
    #pragma unroll
    for (int stage = 0; stage < 10; ++stage) {
        const int half = 1 << stage;
        #pragma unroll
        for (int r = 0; r < 2; ++r) {
            int b = tid + (r << 8);
            int pos = b & (half - 1);
            int i0 = ((b >> stage) << (stage + 1)) + pos;
            int i1 = i0 + half;
            float ang = sign * 3.14159265358979323846f * (float)pos / (float)half;
            float sn, cs;
            sincosf(ang, &sn, &cs);
            float2 x1 = s[i1];
            float2 t = make_float2(x1.x * cs - x1.y * sn, x1.x * sn + x1.y * cs);
            float2 x0 = s[i0];
            s[i0] = make_float2(x0.x + t.x, x0.y + t.y);
            s[i1] = make_float2(x0.x - t.x, x0.y - t.y);
        }
        __syncthreads();
    }
}

__global__ __launch_bounds__(256) void fft_attn_kernel(
    const float* __restrict__ Q, const float* __restrict__ Kx,
    const float* __restrict__ V, float* __restrict__ Out)
{
    __shared__ float2 Z[1024];
    __shared__ float2 Aw[1024];
    const int row = blockIdx.x;
    const int tid = threadIdx.x;
    const float* qr = Q  + (size_t)row * Pd;
    const float* kr = Kx + (size_t)row * Pd;
    const float* vr = V  + (size_t)row * Pd;

    // pack z = q + i*k, bit-reversed load
    for (int i = tid; i < 1024; i += 256) {
        int rdx = __brev((unsigned)i) >> 22;
        Z[rdx] = make_float2(qr[i], kr[i]);
    }
    __syncthreads();
    fft1024_stages(Z, tid, -1.0f);

    // unpack Q,K; Aw = K * conj(Q) / sqrt(P)
    const float inv_scale = 1.0f / 32.0f;   // 1/sqrt(1024)
    for (int i = tid; i < 1024; i += 256) {
        float2 zj = Z[i];
        float2 zn = Z[(1024 - i) & 1023];
        float Qx = 0.5f * (zj.x + zn.x);
        float Qy = 0.5f * (zj.y - zn.y);
        float Kxr = 0.5f * (zj.y + zn.y);
        float Kyr = -0.5f * (zj.x - zn.x);
        float Ax = Kxr * Qx + Kyr * Qy;
        float Ay = Kyr * Qx - Kxr * Qy;
        Aw[i] = make_float2(Ax * inv_scale, Ay * inv_scale);
    }
    __syncthreads();   // all reads of Z done before reuse

    // FFT(v)
    for (int i = tid; i < 1024; i += 256) {
        int rdx = __brev((unsigned)i) >> 22;
        Z[rdx] = make_float2(vr[i], 0.0f);
    }
    __syncthreads();
    fft1024_stages(Z, tid, -1.0f);

    // weighted = Aw * Vf   (into Aw, natural order)
    for (int i = tid; i < 1024; i += 256) {
        float2 vf = Z[i], a = Aw[i];
        Aw[i] = make_float2(vf.x * a.x - vf.y * a.y, vf.x * a.y + vf.y * a.x);
    }
    __syncthreads();

    // bit-reverse into Z, inverse FFT
    for (int i = tid; i < 1024; i += 256) {
        int rdx = __brev((unsigned)i) >> 22;
        Z[rdx] = Aw[i];
    }
    __syncthreads();
    fft1024_stages(Z, tid, +1.0f);

    float* orow = Out + (size_t)row * Pd;
    const float invN = 1.0f / 1024.0f;
    for (int i = tid; i < 1024; i += 256)
        orow[i] = Z[i].x * invN;
}

// ---------------- launch ----------------
extern "C" void kernel_launch(void* const* d_in, const int* in_sizes, int n_in,
                              void* d_out, int out_size) {
    const float* x      = (const float*)d_in[0];
    const float* conv_w = (const float*)d_in[1];
    const float* conv_b = (const float*)d_in[2];
    const float* wq     = (const float*)d_in[3];
    const float* bq     = (const float*)d_in[4];
    const float* wk     = (const float*)d_in[5];
    const float* bk     = (const float*)d_in[6];
    const float* wv     = (const float*)d_in[7];
    const float* bv     = (const float*)d_in[8];
    const float* wo     = (const float*)d_in[9];
    const float* bo     = (const float*)d_in[10];
    float* out = (float*)d_out;

    float *c, *xb, *q, *k, *v, *p, *wavg, *bavg;
    cudaGetSymbolAddress((void**)&c,    g_c);
    cudaGetSymbolAddress((void**)&xb,   g_x);
    cudaGetSymbolAddress((void**)&q,    g_q);
    cudaGetSymbolAddress((void**)&k,    g_k);
    cudaGetSymbolAddress((void**)&v,    g_v);
    cudaGetSymbolAddress((void**)&p,    g_p);
    cudaGetSymbolAddress((void**)&wavg, g_wavg);
    cudaGetSymbolAddress((void**)&bavg, g_bavg);

    avg_conv_kernel<<<1, 64>>>(conv_w, conv_b, wavg, bavg);

    dim3 gq(Pd / BN, ROWS / BM);   // (8, 32)  qkv projections
    dim3 go(Wd / BN, ROWS / BM);   // (16, 32) output projection

    for (int l = 0; l < Ld; l++) {
        const float* xin = (l == 0) ? x : xb;
        float* xout = (l == Ld - 1) ? out : xb;

        conv_row_kernel<<<ROWS, 256>>>(xin, c, wavg + l * Kc, bavg + l);

        gemm_abt_kernel<<<gq, 256>>>(c, wq + (size_t)l * Pd * Wd, bq + (size_t)l * Pd, q, ROWS, Pd, Wd);
        gemm_abt_kernel<<<gq, 256>>>(c, wk + (size_t)l * Pd * Wd, bk + (size_t)l * Pd, k, ROWS, Pd, Wd);
        gemm_abt_kernel<<<gq, 256>>>(c, wv + (size_t)l * Pd * Wd, bv + (size_t)l * Pd, v, ROWS, Pd, Wd);

        fft_attn_kernel<<<ROWS, 256>>>(q, k, v, p);

        gemm_abt_kernel<<<go, 256>>>(p, wo + (size_t)l * Wd * Pd, bo + (size_t)l * Wd, xout, ROWS, Wd, Pd);
    }
}

// round 3
// speedup vs baseline: 1.4387x; 1.4387x over previous
#include <cuda_runtime.h>
#include <cstdint>

#define BSZ 32
#define CNT 128
#define Wd  2048
#define Pd  1024
#define Ed  8
#define Kc  25
#define Ld  2
#define ROWS (BSZ*CNT)   // 4096

// ---------------- scratch ----------------
__device__ float g_c[ROWS*Wd];
__device__ float g_x[ROWS*Wd];
__device__ float g_q[ROWS*Pd];
__device__ float g_k[ROWS*Pd];
__device__ float g_v[ROWS*Pd];
__device__ float g_p[ROWS*Pd];
__device__ float g_wavg[Ld*Kc];
__device__ float g_bavg[Ld];

// ---------------- avg conv weights over experts ----------------
__global__ void avg_conv_kernel(const float* __restrict__ cw, const float* __restrict__ cb,
                                float* __restrict__ wavg, float* __restrict__ bavg) {
    int idx = threadIdx.x;
    if (idx < Ld * Kc) {
        int l = idx / Kc, kk = idx % Kc;
        float s = 0.f;
        #pragma unroll
        for (int e = 0; e < Ed; e++) s += cw[(l * Ed + e) * Kc + kk];
        wavg[idx] = s * (1.0f / Ed);
    }
    if (idx < Ld) {
        float s = 0.f;
        #pragma unroll
        for (int e = 0; e < Ed; e++) s += cb[idx * Ed + e];
        bavg[idx] = s * (1.0f / Ed);
    }
}

// ---------------- 1D conv ----------------
__global__ __launch_bounds__(256) void conv_row_kernel(
    const float* __restrict__ X, float* __restrict__ Y,
    const float* __restrict__ wavg, const float* __restrict__ bavg)
{
    __shared__ float sx[Wd + Kc - 1];
    __shared__ float wsh[Kc];
    const int row = blockIdx.x;
    const int tid = threadIdx.x;
    const float* xr = X + (size_t)row * Wd;

    for (int i = tid; i < Wd + Kc - 1; i += 256) {
        int src = i - (Kc / 2);
        sx[i] = (src >= 0 && src < Wd) ? xr[src] : 0.0f;
    }
    if (tid < Kc) wsh[tid] = wavg[tid];
    __syncthreads();

    const float b = bavg[0];
    float* yr = Y + (size_t)row * Wd;
    for (int h = tid; h < Wd; h += 256) {
        float s = b;
        #pragma unroll
        for (int k = 0; k < Kc; k++) s += sx[h + k] * wsh[k];
        yr[h] = s;
    }
}

// ---------------- 3xTF32 mma.sync GEMM: C[M,N] = A[M,Kd]*B[N,Kd]^T + bias ----------------
__device__ __forceinline__ uint32_t f2tf32(float x) {
    uint32_t r;
    asm("cvt.rna.tf32.f32 %0, %1;" : "=r"(r) : "f"(x));
    return r;
}

#define MMA8(cc, aa, bb) \
    asm volatile("mma.sync.aligned.m16n8k8.row.col.f32.tf32.tf32.f32 " \
        "{%0,%1,%2,%3},{%4,%5,%6,%7},{%8,%9},{%0,%1,%2,%3};" \
        : "+f"((cc)[0]), "+f"((cc)[1]), "+f"((cc)[2]), "+f"((cc)[3]) \
        : "r"((aa)[0]), "r"((aa)[1]), "r"((aa)[2]), "r"((aa)[3]), \
          "r"((bb)[0]), "r"((bb)[1]))

#define RS   36                // smem row stride (floats): conflict-free frag loads
#define TILE (128*RS)          // one 128x32 matrix (padded), in u32 elements
#define SBUF (4*TILE)          // Ahi, Alo, Bhi, Blo
#define GEMM_SMEM (2*SBUF*4)   // double buffered, bytes

__global__ __launch_bounds__(512, 1) void gemm_mma_kernel(
    const float* __restrict__ A, const float* __restrict__ B,
    const float* __restrict__ bias, float* __restrict__ C, int Kd, int N)
{
    extern __shared__ uint32_t sm[];
    const int tid = threadIdx.x;
    const int wid = tid >> 5, lane = tid & 31;
    const int g = lane >> 2, t = lane & 3;
    const int wm = (wid >> 2) * 32;   // warp m-offset (4 warp-rows)
    const int wn = (wid & 3) * 32;    // warp n-offset (4 warp-cols)
    const int bm = blockIdx.y * 128, bn = blockIdx.x * 128;

    // global load mapping: two float4 per matrix per thread
    const int rA = tid >> 3;          // 0..63
    const int c4 = tid & 7;           // 0..7

    const float* Ag = A + (size_t)bm * Kd;
    const float* Bg = B + (size_t)bn * Kd;

    float c[2][4][4];
    #pragma unroll
    for (int mt = 0; mt < 2; mt++)
        #pragma unroll
        for (int nt = 0; nt < 4; nt++)
            #pragma unroll
            for (int e = 0; e < 4; e++) c[mt][nt][e] = 0.0f;

    const int NC = Kd / 32;

    float4 pa[2], pb[2];
    // load chunk 0
    #pragma unroll
    for (int j = 0; j < 2; j++) {
        pa[j] = *(const float4*)(Ag + (size_t)(rA + j * 64) * Kd + c4 * 4);
        pb[j] = *(const float4*)(Bg + (size_t)(rA + j * 64) * Kd + c4 * 4);
    }

    for (int i = 0; i < NC; i++) {
        const int buf = i & 1;
        uint32_t* sAh = sm + buf * SBUF;
        uint32_t* sAl = sAh + TILE;
        uint32_t* sBh = sAl + TILE;
        uint32_t* sBl = sBh + TILE;

        // split + store current prefetch
        #pragma unroll
        for (int j = 0; j < 2; j++) {
            int base = (rA + j * 64) * RS + c4 * 4;
            float av[4] = {pa[j].x, pa[j].y, pa[j].z, pa[j].w};
            float bv[4] = {pb[j].x, pb[j].y, pb[j].z, pb[j].w};
            #pragma unroll
            for (int e = 0; e < 4; e++) {
                uint32_t ah = f2tf32(av[e]);
                sAh[base + e] = ah;
                sAl[base + e] = f2tf32(av[e] - __uint_as_float(ah));
                uint32_t bh = f2tf32(bv[e]);
                sBh[base + e] = bh;
                sBl[base + e] = f2tf32(bv[e] - __uint_as_float(bh));
            }
        }
        __syncthreads();

        // prefetch next chunk
        if (i + 1 < NC) {
            const int k0 = (i + 1) * 32;
            #pragma unroll
            for (int j = 0; j < 2; j++) {
                pa[j] = *(const float4*)(Ag + (size_t)(rA + j * 64) * Kd + c4 * 4 + k0);
                pb[j] = *(const float4*)(Bg + (size_t)(rA + j * 64) * Kd + c4 * 4 + k0);
            }
        }

        // compute 4 k8-steps
        #pragma unroll
        for (int ks = 0; ks < 4; ks++) {
            const int kk = ks * 8;
            uint32_t ah[2][4], al[2][4], bh[4][2], bl[4][2];
            #pragma unroll
            for (int mt = 0; mt < 2; mt++) {
                int m0 = (wm + mt * 16 + g) * RS + kk + t;
                int m8 = m0 + 8 * RS;
                ah[mt][0] = sAh[m0];     ah[mt][1] = sAh[m8];
                ah[mt][2] = sAh[m0 + 4]; ah[mt][3] = sAh[m8 + 4];
                al[mt][0] = sAl[m0];     al[mt][1] = sAl[m8];
                al[mt][2] = sAl[m0 + 4]; al[mt][3] = sAl[m8 + 4];
            }
            #pragma unroll
            for (int nt = 0; nt < 4; nt++) {
                int n0 = (wn + nt * 8 + g) * RS + kk + t;
                bh[nt][0] = sBh[n0]; bh[nt][1] = sBh[n0 + 4];
                bl[nt][0] = sBl[n0]; bl[nt][1] = sBl[n0 + 4];
            }
            #pragma unroll
            for (int mt = 0; mt < 2; mt++)
                #pragma unroll
                for (int nt = 0; nt < 4; nt++) {
                    MMA8(c[mt][nt], ah[mt], bh[nt]);
                    MMA8(c[mt][nt], al[mt], bh[nt]);
                    MMA8(c[mt][nt], ah[mt], bl[nt]);
                }
        }
        __syncthreads();
    }

    // epilogue
    #pragma unroll
    for (int mt = 0; mt < 2; mt++) {
        #pragma unroll
        for (int nt = 0; nt < 4; nt++) {
            int col = bn + wn + nt * 8 + 2 * t;
            float b0 = __ldg(&bias[col]);
            float b1 = __ldg(&bias[col + 1]);
            float* p0 = C + (size_t)(bm + wm + mt * 16 + g) * N + col;
            float2 o0 = make_float2(c[mt][nt][0] + b0, c[mt][nt][1] + b1);
            float2 o1 = make_float2(c[mt][nt][2] + b0, c[mt][nt][3] + b1);
            *(float2*)p0 = o0;
            *(float2*)(p0 + 8 * N) = o1;
        }
    }
}

// ---------------- FFT attention ----------------
__device__ __forceinline__ void fft1024_stages(float2* s, int tid, float sign) {
    #pragma unroll
    for (int stage = 0; stage < 10; ++stage) {
        const int half = 1 << stage;
        #pragma unroll
        for (int r = 0; r < 2; ++r) {
            int b = tid + (r << 8);
            int pos = b & (half - 1);
            int i0 = ((b >> stage) << (stage + 1)) + pos;
            int i1 = i0 + half;
            float ang = sign * 3.14159265358979323846f * (float)pos / (float)half;
            float sn, cs;
            __sincosf(ang, &sn, &cs);
            float2 x1 = s[i1];
            float2 t = make_float2(x1.x * cs - x1.y * sn, x1.x * sn + x1.y * cs);
            float2 x0 = s[i0];
            s[i0] = make_float2(x0.x + t.x, x0.y + t.y);
            s[i1] = make_float2(x0.x - t.x, x0.y - t.y);
        }
        __syncthreads();
    }
}

__global__ __launch_bounds__(256) void fft_attn_kernel(
    const float* __restrict__ Q, const float* __restrict__ Kx,
    const float* __restrict__ V, float* __restrict__ Out)
{
    __shared__ float2 Z[1024];
    __shared__ float2 Aw[1024];
    const int row = blockIdx.x;
    const int tid = threadIdx.x;
    const float* qr = Q  + (size_t)row * Pd;
    const float* kr = Kx + (size_t)row * Pd;
    const float* vr = V  + (size_t)row * Pd;

    for (int i = tid; i < 1024; i += 256) {
        int rdx = __brev((unsigned)i) >> 22;
        Z[rdx] = make_float2(qr[i], kr[i]);
    }
    __syncthreads();
    fft1024_stages(Z, tid, -1.0f);

    const float inv_scale = 1.0f / 32.0f;
    for (int i = tid; i < 1024; i += 256) {
        float2 zj = Z[i];
        float2 zn = Z[(1024 - i) & 1023];
        float Qx = 0.5f * (zj.x + zn.x);
        float Qy = 0.5f * (zj.y - zn.y);
        float Kxr = 0.5f * (zj.y + zn.y);
        float Kyr = -0.5f * (zj.x - zn.x);
        float Ax = Kxr * Qx + Kyr * Qy;
        float Ay = Kyr * Qx - Kxr * Qy;
        Aw[i] = make_float2(Ax * inv_scale, Ay * inv_scale);
    }
    __syncthreads();

    for (int i = tid; i < 1024; i += 256) {
        int rdx = __brev((unsigned)i) >> 22;
        Z[rdx] = make_float2(vr[i], 0.0f);
    }
    __syncthreads();
    fft1024_stages(Z, tid, -1.0f);

    for (int i = tid; i < 1024; i += 256) {
        float2 vf = Z[i], a = Aw[i];
        Aw[i] = make_float2(vf.x * a.x - vf.y * a.y, vf.x * a.y + vf.y * a.x);
    }
    __syncthreads();

    for (int i = tid; i < 1024; i += 256) {
        int rdx = __brev((unsigned)i) >> 22;
        Z[rdx] = Aw[i];
    }
    __syncthreads();
    fft1024_stages(Z, tid, +1.0f);

    float* orow = Out + (size_t)row * Pd;
    const float invN = 1.0f / 1024.0f;
    for (int i = tid; i < 1024; i += 256)
        orow[i] = Z[i].x * invN;
}

// ---------------- launch ----------------
extern "C" void kernel_launch(void* const* d_in, const int* in_sizes, int n_in,
                              void* d_out, int out_size) {
    (void)in_sizes; (void)n_in; (void)out_size;
    const float* x      = (const float*)d_in[0];
    const float* conv_w = (const float*)d_in[1];
    const float* conv_b = (const float*)d_in[2];
    const float* wq     = (const float*)d_in[3];
    const float* bq     = (const float*)d_in[4];
    const float* wk     = (const float*)d_in[5];
    const float* bk     = (const float*)d_in[6];
    const float* wv     = (const float*)d_in[7];
    const float* bv     = (const float*)d_in[8];
    const float* wo     = (const float*)d_in[9];
    const float* bo     = (const float*)d_in[10];
    float* out = (float*)d_out;

    float *c, *xb, *q, *k, *v, *p, *wavg, *bavg;
    cudaGetSymbolAddress((void**)&c,    g_c);
    cudaGetSymbolAddress((void**)&xb,   g_x);
    cudaGetSymbolAddress((void**)&q,    g_q);
    cudaGetSymbolAddress((void**)&k,    g_k);
    cudaGetSymbolAddress((void**)&v,    g_v);
    cudaGetSymbolAddress((void**)&p,    g_p);
    cudaGetSymbolAddress((void**)&wavg, g_wavg);
    cudaGetSymbolAddress((void**)&bavg, g_bavg);

    cudaFuncSetAttribute(gemm_mma_kernel,
                         cudaFuncAttributeMaxDynamicSharedMemorySize, GEMM_SMEM);

    avg_conv_kernel<<<1, 64>>>(conv_w, conv_b, wavg, bavg);

    dim3 gq(Pd / 128, ROWS / 128);   // (8, 32)
    dim3 go(Wd / 128, ROWS / 128);   // (16, 32)

    for (int l = 0; l < Ld; l++) {
        const float* xin = (l == 0) ? x : xb;
        float* xout = (l == Ld - 1) ? out : xb;

        conv_row_kernel<<<ROWS, 256>>>(xin, c, wavg + l * Kc, bavg + l);

        gemm_mma_kernel<<<gq, 512, GEMM_SMEM>>>(c, wq + (size_t)l * Pd * Wd, bq + (size_t)l * Pd, q, Wd, Pd);
        gemm_mma_kernel<<<gq, 512, GEMM_SMEM>>>(c, wk + (size_t)l * Pd * Wd, bk + (size_t)l * Pd, k, Wd, Pd);
        gemm_mma_kernel<<<gq, 512, GEMM_SMEM>>>(c, wv + (size_t)l * Pd * Wd, bv + (size_t)l * Pd, v, Wd, Pd);

        fft_attn_kernel<<<ROWS, 256>>>(q, k, v, p);

        gemm_mma_kernel<<<go, 512, GEMM_SMEM>>>(p, wo + (size_t)l * Wd * Pd, bo + (size_t)l * Wd, xout, Pd, Wd);
    }
}